// round 15
// baseline (speedup 1.0000x reference)
#include <cuda_runtime.h>
#include <cstdint>

// ChamferDistance on GB300 — Round 15: exact NN, warp-granular pruned scan.
// vs R14: QP=4 (128 queries/warp -> 4 independent FFMA2 chains, fma-pipe
// saturating at low occupancy) and fixed z-range bucketing (no min/max pass).
// Exact: clamped outliers land in edge buckets; all bucket-edge bounds hold.

#define NB    256
#define ST    256
#define QP    4
#define WQ    (32 * QP)    // 128 queries per warp
#define TW    64           // refs per tile (1KB smem)
#define BSTEP 2
#define PAD   2
#define MAXP  8192
#define MAXB  8

#define ZMIN_FIX (-6.0f)
#define ZW_FIX   (12.0f / NB)
#define ZINVW_FIX (NB / 12.0f)

__device__ float g_sx [2][MAXB * MAXP];
__device__ float g_sy [2][MAXB * MAXP];
__device__ float g_sz [2][MAXB * MAXP];
__device__ float g_sq [2][MAXB * MAXP];
__device__ int   g_idx[2][MAXB * MAXP];
__device__ int   g_off[2][MAXB][NB + 1];

// ---------------- Stage 1: z counting sort, fixed range ----------------
__global__ __launch_bounds__(ST)
void cd_bucket_kernel(const float* __restrict__ xyz1,
                      const float* __restrict__ xyz2,
                      int Npts)
{
    const int set = blockIdx.y;
    const int b   = blockIdx.x;
    const float* __restrict__ src =
        ((set == 0) ? xyz1 : xyz2) + (size_t)b * Npts * 3;
    const int tid = threadIdx.x;

    __shared__ int s_hist[NB];
    __shared__ int s_off[NB + 1];
    __shared__ int s_cur[NB];

    if (tid < NB) s_hist[tid] = 0;
    __syncthreads();

    for (int j = tid; j < Npts; j += ST) {
        float z = src[j * 3 + 2];
        int bb = min(NB - 1, max(0, (int)((z - ZMIN_FIX) * ZINVW_FIX)));
        atomicAdd(&s_hist[bb], 1);
    }
    __syncthreads();
    if (tid == 0) {
        int acc = 0;
        for (int i = 0; i < NB; i++) { s_off[i] = acc; acc += s_hist[i]; }
        s_off[NB] = acc;
    }
    __syncthreads();
    if (tid < NB) s_cur[tid] = s_off[tid];
    if (tid < NB) g_off[set][b][tid] = s_off[tid];
    if (tid == 0) g_off[set][b][NB] = s_off[NB];
    __syncthreads();

    const size_t bo = (size_t)b * Npts;
    for (int j = tid; j < Npts; j += ST) {
        float x = src[j * 3 + 0];
        float y = src[j * 3 + 1];
        float z = src[j * 3 + 2];
        int bb = min(NB - 1, max(0, (int)((z - ZMIN_FIX) * ZINVW_FIX)));
        int pos = atomicAdd(&s_cur[bb], 1);
        g_sx[set][bo + pos] = x;
        g_sy[set][bo + pos] = y;
        g_sz[set][bo + pos] = z;
        g_sq[set][bo + pos] = fmaf(x, x, fmaf(y, y, z * z));
        g_idx[set][bo + pos] = j;
    }
}

// ---------------- helpers ----------------
__device__ __forceinline__ uint64_t cd_dup2(float v) {
    uint64_t r;
    asm("mov.b64 %0, {%1, %1};" : "=l"(r) : "r"(__float_as_uint(v)));
    return r;
}

__device__ __forceinline__ void cd_dot2(uint64_t qx, uint64_t qy, uint64_t qz,
                                        uint64_t px, uint64_t py, uint64_t pz,
                                        uint64_t s,
                                        float& dlo, float& dhi) {
    uint32_t lo, hi;
    asm("{\n\t"
        ".reg .b64 t;\n\t"
        "fma.rn.f32x2 t, %2, %3, %4;\n\t"
        "fma.rn.f32x2 t, %5, %6, t;\n\t"
        "fma.rn.f32x2 t, %7, %8, t;\n\t"
        "mov.b64 {%0, %1}, t;\n\t"
        "}"
        : "=r"(lo), "=r"(hi)
        : "l"(qz), "l"(pz), "l"(s),
          "l"(qy), "l"(py),
          "l"(qx), "l"(px));
    dlo = __uint_as_float(lo);
    dhi = __uint_as_float(hi);
}

__device__ __forceinline__ float wmax(float v) {
    #pragma unroll
    for (int o = 16; o; o >>= 1) v = fmaxf(v, __shfl_xor_sync(0xFFFFFFFFu, v, o));
    return v;
}
__device__ __forceinline__ float wmin(float v) {
    #pragma unroll
    for (int o = 16; o; o >>= 1) v = fminf(v, __shfl_xor_sync(0xFFFFFFFFu, v, o));
    return v;
}

// ---------------- Stage 2: warp-granular pruned NN (32 thr/CTA) ----------
__global__ __launch_bounds__(32, 16)
void cd_nn_kernel(float* __restrict__ out, int Npts, int B)
{
    const int dir  = blockIdx.z;
    const int b    = blockIdx.y;
    const int qset = dir, rset = 1 - dir;
    const int lane = threadIdx.x;

    const size_t qo = (size_t)b * Npts;
    const float* __restrict__ QX = &g_sx[qset][qo];
    const float* __restrict__ QY = &g_sy[qset][qo];
    const float* __restrict__ QZ = &g_sz[qset][qo];
    const float* __restrict__ QS = &g_sq[qset][qo];
    const int*   __restrict__ QI = &g_idx[qset][qo];

    const float4* __restrict__ RX4 = (const float4*)&g_sx[rset][qo];
    const float4* __restrict__ RY4 = (const float4*)&g_sy[rset][qo];
    const float4* __restrict__ RZ4 = (const float4*)&g_sz[rset][qo];
    const float4* __restrict__ RQ4 = (const float4*)&g_sq[rset][qo];
    const int* __restrict__ off = g_off[rset][b];

    __shared__ __align__(16) float sw[4 * TW];

    const int qbase = blockIdx.x * WQ;

    uint64_t qxd[QP], qyd[QP], qzd[QP];
    float qsq[QP], zq[QP], me[QP];
    #pragma unroll
    for (int p = 0; p < QP; p++) {
        int ii = qbase + p * 32 + lane;
        float x = QX[ii], y = QY[ii], z = QZ[ii];
        qxd[p] = cd_dup2(-2.0f * x);
        qyd[p] = cd_dup2(-2.0f * y);
        qzd[p] = cd_dup2(-2.0f * z);
        qsq[p] = QS[ii];
        zq[p]  = z;
        me[p]  = 3.402823466e+38f;
    }

    float zt0 = fminf(fminf(zq[0], zq[1]), fminf(zq[2], zq[3]));
    float zt1 = fmaxf(fmaxf(zq[0], zq[1]), fmaxf(zq[2], zq[3]));
    float zqmin = wmin(zt0);
    float zqmax = wmax(zt1);

    // Staging roles: lanes 0-15 load x+z chunks, lanes 16-31 load y+sq.
    const int k4 = (lane & 15) << 2;
    const int hi = lane >> 4;
    const float4* __restrict__ SA = hi ? RY4 : RX4;
    const float4* __restrict__ SB = hi ? RQ4 : RZ4;
    const float padB = hi ? 3.402823466e+38f : 0.0f;

    float4 ra, rb;

    auto ldtile = [&](int jt, int j1a) {
        int idx = jt + k4;
        if (idx < j1a) {
            ra = SA[idx >> 2];
            rb = SB[idx >> 2];
        } else {
            ra = make_float4(0.f, 0.f, 0.f, 0.f);
            rb = make_float4(padB, padB, padB, padB);
        }
    };

    auto scan = [&](int j0, int j1) {
        j0 &= ~3;
        j1 = min((j1 + 3) & ~3, Npts);
        if (j0 >= j1) return;
        ldtile(j0, j1);
        for (int jt = j0; jt < j1; jt += TW) {
            __syncwarp();
            *(float4*)&sw[hi * TW + k4]       = ra;
            *(float4*)&sw[(2 + hi) * TW + k4] = rb;
            __syncwarp();
            int nx = jt + TW;
            if (nx < j1) ldtile(nx, j1);
            const uint64_t* __restrict__ px2 = (const uint64_t*)&sw[0];
            const uint64_t* __restrict__ py2 = (const uint64_t*)&sw[TW];
            const uint64_t* __restrict__ pz2 = (const uint64_t*)&sw[2 * TW];
            const uint64_t* __restrict__ ps2 = (const uint64_t*)&sw[3 * TW];
            #pragma unroll 2
            for (int jj = 0; jj < TW / 2; jj++) {
                uint64_t px = px2[jj], py = py2[jj];
                uint64_t pz = pz2[jj], ps = ps2[jj];
                #pragma unroll
                for (int p = 0; p < QP; p++) {
                    float dlo, dhi2;
                    cd_dot2(qxd[p], qyd[p], qzd[p], px, py, pz, ps, dlo, dhi2);
                    me[p] = fminf(me[p], fminf(dlo, dhi2));
                }
            }
        }
        __syncwarp();
    };

    int bq_lo = min(NB - 1, max(0, (int)((zqmin - ZMIN_FIX) * ZINVW_FIX)));
    int bq_hi = min(NB - 1, max(0, (int)((zqmax - ZMIN_FIX) * ZINVW_FIX)));
    int blo = max(bq_lo - PAD, 0);
    int bhi = min(bq_hi + 1 + PAD, NB);
    scan(off[blo], off[bhi]);

    for (;;) {
        float hn = -3.402823466e+38f, ln = 3.402823466e+38f;
        #pragma unroll
        for (int p = 0; p < QP; p++) {
            float r = sqrtf(fmaxf(me[p] + qsq[p], 0.0f));
            hn = fmaxf(hn, zq[p] + r);
            ln = fminf(ln, zq[p] - r);
        }
        float hi_need = wmax(hn);
        float lo_need = wmin(ln);

        bool okLo = (blo > 0)  && (ZMIN_FIX + (float)blo * ZW_FIX > lo_need);
        bool okHi = (bhi < NB) && (ZMIN_FIX + (float)bhi * ZW_FIX < hi_need);
        if (!okLo && !okHi) break;
        if (okLo) {
            int nlo = max(blo - BSTEP, 0);
            scan(off[nlo], off[blo]);
            blo = nlo;
        }
        if (okHi) {
            int nhi = min(bhi + BSTEP, NB);
            scan(off[bhi], off[nhi]);
            bhi = nhi;
        }
    }

    float* __restrict__ o = out + ((dir == 0) ? 0 : (size_t)B * Npts)
                          + (size_t)b * Npts;
    #pragma unroll
    for (int p = 0; p < QP; p++) {
        float d = fmaxf(me[p] + qsq[p], 0.0f);
        o[QI[qbase + p * 32 + lane]] = d;
    }
}

extern "C" void kernel_launch(void* const* d_in, const int* in_sizes, int n_in,
                              void* d_out, int out_size)
{
    const float* xyz1 = (const float*)d_in[0];
    const float* xyz2 = (const float*)d_in[1];
    float* out = (float*)d_out;

    const int B = 8;
    const int N = (in_sizes[0] / 3) / B;   // 8192 (== M)

    {
        dim3 grid(B, 2);
        cd_bucket_kernel<<<grid, ST>>>(xyz1, xyz2, N);
    }
    {
        int qblocks = N / WQ;                 // 64 warps per (b,dir)
        dim3 grid(qblocks, B, 2);             // 64 x 8 x 2 = 1024 CTAs
        cd_nn_kernel<<<grid, 32>>>(out, N, B);
    }
}

// round 16
// speedup vs baseline: 1.4272x; 1.4272x over previous
#include <cuda_runtime.h>
#include <cstdint>

// ChamferDistance on GB300 — Round 16: exact NN, warp-granular pruned scan.
// = R14 (QP=2, 2048 warp-CTAs, smem staging + prefetch) with:
//   * vote-based window termination (no sqrt, no shfl-reduce)  
//   * BSTEP=4, fixed-range z bucketing (no min/max pass)

#define NB    256
#define ST    256
#define QP    2
#define WQ    (32 * QP)    // 64 queries per warp
#define TW    64           // refs per tile (1KB smem)
#define BSTEP 4
#define PAD   2
#define MAXP  8192
#define MAXB  8

#define ZMIN_FIX  (-6.0f)
#define ZW_FIX    (12.0f / NB)
#define ZINVW_FIX (NB / 12.0f)

__device__ float g_sx [2][MAXB * MAXP];
__device__ float g_sy [2][MAXB * MAXP];
__device__ float g_sz [2][MAXB * MAXP];
__device__ float g_sq [2][MAXB * MAXP];
__device__ int   g_idx[2][MAXB * MAXP];
__device__ int   g_off[2][MAXB][NB + 1];

// ---------------- Stage 1: z counting sort, fixed range ----------------
__global__ __launch_bounds__(ST)
void cd_bucket_kernel(const float* __restrict__ xyz1,
                      const float* __restrict__ xyz2,
                      int Npts)
{
    const int set = blockIdx.y;
    const int b   = blockIdx.x;
    const float* __restrict__ src =
        ((set == 0) ? xyz1 : xyz2) + (size_t)b * Npts * 3;
    const int tid = threadIdx.x;

    __shared__ int s_hist[NB];
    __shared__ int s_off[NB + 1];
    __shared__ int s_cur[NB];

    if (tid < NB) s_hist[tid] = 0;
    __syncthreads();

    for (int j = tid; j < Npts; j += ST) {
        float z = src[j * 3 + 2];
        int bb = min(NB - 1, max(0, (int)((z - ZMIN_FIX) * ZINVW_FIX)));
        atomicAdd(&s_hist[bb], 1);
    }
    __syncthreads();
    if (tid == 0) {
        int acc = 0;
        for (int i = 0; i < NB; i++) { s_off[i] = acc; acc += s_hist[i]; }
        s_off[NB] = acc;
    }
    __syncthreads();
    if (tid < NB) s_cur[tid] = s_off[tid];
    if (tid < NB) g_off[set][b][tid] = s_off[tid];
    if (tid == 0) g_off[set][b][NB] = s_off[NB];
    __syncthreads();

    const size_t bo = (size_t)b * Npts;
    for (int j = tid; j < Npts; j += ST) {
        float x = src[j * 3 + 0];
        float y = src[j * 3 + 1];
        float z = src[j * 3 + 2];
        int bb = min(NB - 1, max(0, (int)((z - ZMIN_FIX) * ZINVW_FIX)));
        int pos = atomicAdd(&s_cur[bb], 1);
        g_sx[set][bo + pos] = x;
        g_sy[set][bo + pos] = y;
        g_sz[set][bo + pos] = z;
        g_sq[set][bo + pos] = fmaf(x, x, fmaf(y, y, z * z));
        g_idx[set][bo + pos] = j;
    }
}

// ---------------- helpers ----------------
__device__ __forceinline__ uint64_t cd_dup2(float v) {
    uint64_t r;
    asm("mov.b64 %0, {%1, %1};" : "=l"(r) : "r"(__float_as_uint(v)));
    return r;
}

__device__ __forceinline__ void cd_dot2(uint64_t qx, uint64_t qy, uint64_t qz,
                                        uint64_t px, uint64_t py, uint64_t pz,
                                        uint64_t s,
                                        float& dlo, float& dhi) {
    uint32_t lo, hi;
    asm("{\n\t"
        ".reg .b64 t;\n\t"
        "fma.rn.f32x2 t, %2, %3, %4;\n\t"
        "fma.rn.f32x2 t, %5, %6, t;\n\t"
        "fma.rn.f32x2 t, %7, %8, t;\n\t"
        "mov.b64 {%0, %1}, t;\n\t"
        "}"
        : "=r"(lo), "=r"(hi)
        : "l"(qz), "l"(pz), "l"(s),
          "l"(qy), "l"(py),
          "l"(qx), "l"(px));
    dlo = __uint_as_float(lo);
    dhi = __uint_as_float(hi);
}

__device__ __forceinline__ float wmax(float v) {
    #pragma unroll
    for (int o = 16; o; o >>= 1) v = fmaxf(v, __shfl_xor_sync(0xFFFFFFFFu, v, o));
    return v;
}
__device__ __forceinline__ float wmin(float v) {
    #pragma unroll
    for (int o = 16; o; o >>= 1) v = fminf(v, __shfl_xor_sync(0xFFFFFFFFu, v, o));
    return v;
}

// ---------------- Stage 2: warp-granular pruned NN (32 thr/CTA) ----------
__global__ __launch_bounds__(32, 16)
void cd_nn_kernel(float* __restrict__ out, int Npts, int B)
{
    const int dir  = blockIdx.z;
    const int b    = blockIdx.y;
    const int qset = dir, rset = 1 - dir;
    const int lane = threadIdx.x;

    const size_t qo = (size_t)b * Npts;
    const float* __restrict__ QX = &g_sx[qset][qo];
    const float* __restrict__ QY = &g_sy[qset][qo];
    const float* __restrict__ QZ = &g_sz[qset][qo];
    const float* __restrict__ QS = &g_sq[qset][qo];
    const int*   __restrict__ QI = &g_idx[qset][qo];

    const float4* __restrict__ RX4 = (const float4*)&g_sx[rset][qo];
    const float4* __restrict__ RY4 = (const float4*)&g_sy[rset][qo];
    const float4* __restrict__ RZ4 = (const float4*)&g_sz[rset][qo];
    const float4* __restrict__ RQ4 = (const float4*)&g_sq[rset][qo];
    const int* __restrict__ off = g_off[rset][b];

    __shared__ __align__(16) float sw[4 * TW];

    const int qbase = blockIdx.x * WQ;

    uint64_t qxd[QP], qyd[QP], qzd[QP];
    float qsq[QP], zq[QP], me[QP];
    #pragma unroll
    for (int p = 0; p < QP; p++) {
        int ii = qbase + p * 32 + lane;
        float x = QX[ii], y = QY[ii], z = QZ[ii];
        qxd[p] = cd_dup2(-2.0f * x);
        qyd[p] = cd_dup2(-2.0f * y);
        qzd[p] = cd_dup2(-2.0f * z);
        qsq[p] = QS[ii];
        zq[p]  = z;
        me[p]  = 3.402823466e+38f;
    }

    float zqmin = wmin(fminf(zq[0], zq[1]));
    float zqmax = wmax(fmaxf(zq[0], zq[1]));

    // Staging roles: lanes 0-15 load x+z chunks, lanes 16-31 load y+sq.
    const int k4 = (lane & 15) << 2;
    const int hi = lane >> 4;
    const float4* __restrict__ SA = hi ? RY4 : RX4;
    const float4* __restrict__ SB = hi ? RQ4 : RZ4;
    const float padB = hi ? 3.402823466e+38f : 0.0f;

    float4 ra, rb;

    auto ldtile = [&](int jt, int j1a) {
        int idx = jt + k4;
        if (idx < j1a) {
            ra = SA[idx >> 2];
            rb = SB[idx >> 2];
        } else {
            ra = make_float4(0.f, 0.f, 0.f, 0.f);
            rb = make_float4(padB, padB, padB, padB);
        }
    };

    auto scan = [&](int j0, int j1) {
        j0 &= ~3;
        j1 = min((j1 + 3) & ~3, Npts);
        if (j0 >= j1) return;
        ldtile(j0, j1);
        for (int jt = j0; jt < j1; jt += TW) {
            __syncwarp();
            *(float4*)&sw[hi * TW + k4]       = ra;
            *(float4*)&sw[(2 + hi) * TW + k4] = rb;
            __syncwarp();
            int nx = jt + TW;
            if (nx < j1) ldtile(nx, j1);
            const uint64_t* __restrict__ px2 = (const uint64_t*)&sw[0];
            const uint64_t* __restrict__ py2 = (const uint64_t*)&sw[TW];
            const uint64_t* __restrict__ pz2 = (const uint64_t*)&sw[2 * TW];
            const uint64_t* __restrict__ ps2 = (const uint64_t*)&sw[3 * TW];
            #pragma unroll 4
            for (int jj = 0; jj < TW / 2; jj++) {
                uint64_t px = px2[jj], py = py2[jj];
                uint64_t pz = pz2[jj], ps = ps2[jj];
                #pragma unroll
                for (int p = 0; p < QP; p++) {
                    float dlo, dhi2;
                    cd_dot2(qxd[p], qyd[p], qzd[p], px, py, pz, ps, dlo, dhi2);
                    me[p] = fminf(me[p], fminf(dlo, dhi2));
                }
            }
        }
        __syncwarp();
    };

    int bq_lo = min(NB - 1, max(0, (int)((zqmin - ZMIN_FIX) * ZINVW_FIX)));
    int bq_hi = min(NB - 1, max(0, (int)((zqmax - ZMIN_FIX) * ZINVW_FIX)));
    int blo = max(bq_lo - PAD, 0);
    int bhi = min(bq_hi + 1 + PAD, NB);
    scan(off[blo], off[bhi]);

    // Vote-based expansion: need-below <=> exists q with (zq-edgeLo)^2 < dq.
    for (;;) {
        float edgeLo = ZMIN_FIX + (float)blo * ZW_FIX;
        float edgeHi = ZMIN_FIX + (float)bhi * ZW_FIX;
        bool nLo = false, nHi = false;
        #pragma unroll
        for (int p = 0; p < QP; p++) {
            float dq = me[p] + qsq[p];
            float tl = fmaxf(zq[p] - edgeLo, 0.0f);
            float th = fmaxf(edgeHi - zq[p], 0.0f);
            nLo |= (tl * tl < dq);
            nHi |= (th * th < dq);
        }
        bool okLo = (blo > 0)  && __any_sync(0xFFFFFFFFu, nLo);
        bool okHi = (bhi < NB) && __any_sync(0xFFFFFFFFu, nHi);
        if (!okLo && !okHi) break;
        if (okLo) {
            int nlo = max(blo - BSTEP, 0);
            scan(off[nlo], off[blo]);
            blo = nlo;
        }
        if (okHi) {
            int nhi = min(bhi + BSTEP, NB);
            scan(off[bhi], off[nhi]);
            bhi = nhi;
        }
    }

    float* __restrict__ o = out + ((dir == 0) ? 0 : (size_t)B * Npts)
                          + (size_t)b * Npts;
    #pragma unroll
    for (int p = 0; p < QP; p++) {
        float d = fmaxf(me[p] + qsq[p], 0.0f);
        o[QI[qbase + p * 32 + lane]] = d;
    }
}

extern "C" void kernel_launch(void* const* d_in, const int* in_sizes, int n_in,
                              void* d_out, int out_size)
{
    const float* xyz1 = (const float*)d_in[0];
    const float* xyz2 = (const float*)d_in[1];
    float* out = (float*)d_out;

    const int B = 8;
    const int N = (in_sizes[0] / 3) / B;   // 8192 (== M)

    {
        dim3 grid(B, 2);
        cd_bucket_kernel<<<grid, ST>>>(xyz1, xyz2, N);
    }
    {
        int qblocks = N / WQ;                 // 128 warps per (b,dir)
        dim3 grid(qblocks, B, 2);             // 2048 CTAs
        cd_nn_kernel<<<grid, 32>>>(out, N, B);
    }
}

// round 17
// speedup vs baseline: 1.5822x; 1.1086x over previous
#include <cuda_runtime.h>
#include <cstdint>

// ChamferDistance on GB300 — Round 17: exact NN, warp-granular pruned scan.
// vs R16: QP=1 (32 queries/warp -> 4096 CTAs, 2x warps/SM) with a 4-ref
// inner step (LDS.128) keeping 3.5 issues/pair; bucketing parallelized into
// 4 wide kernels (init/hist/scan/scatter) instead of 16 serial CTAs.

#define NB    256
#define SP    8            // point-chunks per (set,batch) for hist/scatter
#define HT    256          // threads for bucket kernels
#define TW    64           // refs per tile (1KB smem)
#define BSTEP 4
#define PAD   2
#define MAXP  8192
#define MAXB  8

#define ZMIN_FIX  (-6.0f)
#define ZW_FIX    (12.0f / NB)
#define ZINVW_FIX (NB / 12.0f)

__device__ float g_sx [2][MAXB * MAXP];
__device__ float g_sy [2][MAXB * MAXP];
__device__ float g_sz [2][MAXB * MAXP];
__device__ float g_sq [2][MAXB * MAXP];
__device__ int   g_idx[2][MAXB * MAXP];
__device__ int   g_hist[2][MAXB][NB];
__device__ int   g_cur [2][MAXB][NB];
__device__ int   g_off [2][MAXB][NB + 1];

// ---------------- Stage 1a: zero histograms ----------------
__global__ void cd_init_hist() {
    int i = blockIdx.x * blockDim.x + threadIdx.x;   // 16*256 = 4096
    ((int*)g_hist)[i] = 0;
}

// ---------------- Stage 1b: histogram (wide) ----------------
__global__ __launch_bounds__(HT)
void cd_hist_kernel(const float* __restrict__ xyz1,
                    const float* __restrict__ xyz2,
                    int Npts)
{
    const int set = blockIdx.y;
    const int b   = blockIdx.x;
    const int c   = blockIdx.z;
    const int tid = threadIdx.x;
    const int chunk = Npts / SP;
    const float* __restrict__ src =
        ((set == 0) ? xyz1 : xyz2) + (size_t)b * Npts * 3 + (size_t)c * chunk * 3;

    __shared__ int s_hist[NB];
    if (tid < NB) s_hist[tid] = 0;
    __syncthreads();

    for (int j = tid; j < chunk; j += HT) {
        float z = src[j * 3 + 2];
        int bb = min(NB - 1, max(0, (int)((z - ZMIN_FIX) * ZINVW_FIX)));
        atomicAdd(&s_hist[bb], 1);
    }
    __syncthreads();
    if (tid < NB && s_hist[tid] > 0)
        atomicAdd(&g_hist[set][b][tid], s_hist[tid]);
}

// ---------------- Stage 1c: scan offsets ----------------
__global__ __launch_bounds__(HT)
void cd_scan_kernel() {
    const int set = blockIdx.y;
    const int b   = blockIdx.x;
    const int tid = threadIdx.x;
    __shared__ int s_off[NB + 1];
    if (tid == 0) {
        int acc = 0;
        for (int i = 0; i < NB; i++) { s_off[i] = acc; acc += g_hist[set][b][i]; }
        s_off[NB] = acc;
    }
    __syncthreads();
    if (tid < NB) {
        g_off[set][b][tid] = s_off[tid];
        g_cur[set][b][tid] = s_off[tid];
    }
    if (tid == 0) g_off[set][b][NB] = s_off[NB];
}

// ---------------- Stage 1d: scatter (wide, global cursors) ----------------
__global__ __launch_bounds__(HT)
void cd_scatter_kernel(const float* __restrict__ xyz1,
                       const float* __restrict__ xyz2,
                       int Npts)
{
    const int set = blockIdx.y;
    const int b   = blockIdx.x;
    const int c   = blockIdx.z;
    const int tid = threadIdx.x;
    const int chunk = Npts / SP;
    const int jbase = c * chunk;
    const float* __restrict__ src =
        ((set == 0) ? xyz1 : xyz2) + (size_t)b * Npts * 3;
    const size_t bo = (size_t)b * Npts;

    for (int j = jbase + tid; j < jbase + chunk; j += HT) {
        float x = src[j * 3 + 0];
        float y = src[j * 3 + 1];
        float z = src[j * 3 + 2];
        int bb = min(NB - 1, max(0, (int)((z - ZMIN_FIX) * ZINVW_FIX)));
        int pos = atomicAdd(&g_cur[set][b][bb], 1);
        g_sx[set][bo + pos] = x;
        g_sy[set][bo + pos] = y;
        g_sz[set][bo + pos] = z;
        g_sq[set][bo + pos] = fmaf(x, x, fmaf(y, y, z * z));
        g_idx[set][bo + pos] = j;
    }
}

// ---------------- helpers ----------------
__device__ __forceinline__ uint64_t cd_dup2(float v) {
    uint64_t r;
    asm("mov.b64 %0, {%1, %1};" : "=l"(r) : "r"(__float_as_uint(v)));
    return r;
}

__device__ __forceinline__ void cd_dot2(uint64_t qx, uint64_t qy, uint64_t qz,
                                        uint64_t px, uint64_t py, uint64_t pz,
                                        uint64_t s,
                                        float& dlo, float& dhi) {
    uint32_t lo, hi;
    asm("{\n\t"
        ".reg .b64 t;\n\t"
        "fma.rn.f32x2 t, %2, %3, %4;\n\t"
        "fma.rn.f32x2 t, %5, %6, t;\n\t"
        "fma.rn.f32x2 t, %7, %8, t;\n\t"
        "mov.b64 {%0, %1}, t;\n\t"
        "}"
        : "=r"(lo), "=r"(hi)
        : "l"(qz), "l"(pz), "l"(s),
          "l"(qy), "l"(py),
          "l"(qx), "l"(px));
    dlo = __uint_as_float(lo);
    dhi = __uint_as_float(hi);
}

__device__ __forceinline__ float wmax(float v) {
    #pragma unroll
    for (int o = 16; o; o >>= 1) v = fmaxf(v, __shfl_xor_sync(0xFFFFFFFFu, v, o));
    return v;
}
__device__ __forceinline__ float wmin(float v) {
    #pragma unroll
    for (int o = 16; o; o >>= 1) v = fminf(v, __shfl_xor_sync(0xFFFFFFFFu, v, o));
    return v;
}

// ---------------- Stage 2: warp-granular pruned NN (QP=1) ----------------
__global__ __launch_bounds__(32, 24)
void cd_nn_kernel(float* __restrict__ out, int Npts, int B)
{
    const int dir  = blockIdx.z;
    const int b    = blockIdx.y;
    const int qset = dir, rset = 1 - dir;
    const int lane = threadIdx.x;

    const size_t qo = (size_t)b * Npts;
    const float* __restrict__ QX = &g_sx[qset][qo];
    const float* __restrict__ QY = &g_sy[qset][qo];
    const float* __restrict__ QZ = &g_sz[qset][qo];
    const float* __restrict__ QS = &g_sq[qset][qo];
    const int*   __restrict__ QI = &g_idx[qset][qo];

    const float4* __restrict__ RX4 = (const float4*)&g_sx[rset][qo];
    const float4* __restrict__ RY4 = (const float4*)&g_sy[rset][qo];
    const float4* __restrict__ RZ4 = (const float4*)&g_sz[rset][qo];
    const float4* __restrict__ RQ4 = (const float4*)&g_sq[rset][qo];
    const int* __restrict__ off = g_off[rset][b];

    __shared__ __align__(16) float sw[4 * TW];

    const int qi = blockIdx.x * 32 + lane;

    float x = QX[qi], y = QY[qi], z = QZ[qi];
    const uint64_t qxd = cd_dup2(-2.0f * x);
    const uint64_t qyd = cd_dup2(-2.0f * y);
    const uint64_t qzd = cd_dup2(-2.0f * z);
    const float qsq = QS[qi];
    const float zq  = z;
    float me = 3.402823466e+38f;

    float zqmin = wmin(zq);
    float zqmax = wmax(zq);

    // Staging roles: lanes 0-15 load x+z chunks, lanes 16-31 load y+sq.
    const int k4 = (lane & 15) << 2;
    const int hi = lane >> 4;
    const float4* __restrict__ SA = hi ? RY4 : RX4;
    const float4* __restrict__ SB = hi ? RQ4 : RZ4;
    const float padB = hi ? 3.402823466e+38f : 0.0f;

    float4 ra, rb;

    auto ldtile = [&](int jt, int j1a) {
        int idx = jt + k4;
        if (idx < j1a) {
            ra = SA[idx >> 2];
            rb = SB[idx >> 2];
        } else {
            ra = make_float4(0.f, 0.f, 0.f, 0.f);
            rb = make_float4(padB, padB, padB, padB);
        }
    };

    auto scan = [&](int j0, int j1) {
        j0 &= ~3;
        j1 = min((j1 + 3) & ~3, Npts);
        if (j0 >= j1) return;
        ldtile(j0, j1);
        for (int jt = j0; jt < j1; jt += TW) {
            __syncwarp();
            *(float4*)&sw[hi * TW + k4]       = ra;
            *(float4*)&sw[(2 + hi) * TW + k4] = rb;
            __syncwarp();
            int nx = jt + TW;
            if (nx < j1) ldtile(nx, j1);
            const ulonglong2* __restrict__ px4 = (const ulonglong2*)&sw[0];
            const ulonglong2* __restrict__ py4 = (const ulonglong2*)&sw[TW];
            const ulonglong2* __restrict__ pz4 = (const ulonglong2*)&sw[2 * TW];
            const ulonglong2* __restrict__ ps4 = (const ulonglong2*)&sw[3 * TW];
            #pragma unroll 4
            for (int j4 = 0; j4 < TW / 4; j4++) {
                ulonglong2 X = px4[j4];   // {x0,x1},{x2,x3} broadcast LDS.128
                ulonglong2 Y = py4[j4];
                ulonglong2 Z = pz4[j4];
                ulonglong2 S = ps4[j4];
                float a0, a1, b0, b1;
                cd_dot2(qxd, qyd, qzd, X.x, Y.x, Z.x, S.x, a0, a1);
                cd_dot2(qxd, qyd, qzd, X.y, Y.y, Z.y, S.y, b0, b1);
                float e = fminf(a0, b0);
                float f = fminf(a1, b1);
                me = fminf(me, fminf(e, f));
            }
        }
        __syncwarp();
    };

    int bq_lo = min(NB - 1, max(0, (int)((zqmin - ZMIN_FIX) * ZINVW_FIX)));
    int bq_hi = min(NB - 1, max(0, (int)((zqmax - ZMIN_FIX) * ZINVW_FIX)));
    int blo = max(bq_lo - PAD, 0);
    int bhi = min(bq_hi + 1 + PAD, NB);
    scan(off[blo], off[bhi]);

    // Vote-based expansion (exact, squared compare).
    for (;;) {
        float edgeLo = ZMIN_FIX + (float)blo * ZW_FIX;
        float edgeHi = ZMIN_FIX + (float)bhi * ZW_FIX;
        float dq = me + qsq;
        float tl = fmaxf(zq - edgeLo, 0.0f);
        float th = fmaxf(edgeHi - zq, 0.0f);
        bool okLo = (blo > 0)  && __any_sync(0xFFFFFFFFu, tl * tl < dq);
        bool okHi = (bhi < NB) && __any_sync(0xFFFFFFFFu, th * th < dq);
        if (!okLo && !okHi) break;
        if (okLo) {
            int nlo = max(blo - BSTEP, 0);
            scan(off[nlo], off[blo]);
            blo = nlo;
        }
        if (okHi) {
            int nhi = min(bhi + BSTEP, NB);
            scan(off[bhi], off[nhi]);
            bhi = nhi;
        }
    }

    float* __restrict__ o = out + ((dir == 0) ? 0 : (size_t)B * Npts)
                          + (size_t)b * Npts;
    o[QI[qi]] = fmaxf(me + qsq, 0.0f);
}

extern "C" void kernel_launch(void* const* d_in, const int* in_sizes, int n_in,
                              void* d_out, int out_size)
{
    const float* xyz1 = (const float*)d_in[0];
    const float* xyz2 = (const float*)d_in[1];
    float* out = (float*)d_out;

    const int B = 8;
    const int N = (in_sizes[0] / 3) / B;   // 8192 (== M)

    cd_init_hist<<<(2 * MAXB * NB) / HT, HT>>>();
    {
        dim3 grid(B, 2, SP);
        cd_hist_kernel<<<grid, HT>>>(xyz1, xyz2, N);
    }
    {
        dim3 grid(B, 2);
        cd_scan_kernel<<<grid, HT>>>();
    }
    {
        dim3 grid(B, 2, SP);
        cd_scatter_kernel<<<grid, HT>>>(xyz1, xyz2, N);
    }
    {
        dim3 grid(N / 32, B, 2);              // 256 x 8 x 2 = 4096 CTAs
        cd_nn_kernel<<<grid, 32>>>(out, N, B);
    }
}